// round 17
// baseline (speedup 1.0000x reference)
#include <cuda_runtime.h>
#include <math.h>

// ---------------------------------------------------------------------------
// Problem shape (fixed): B=256, R=512, D=64, N=100000, E=3200000
// ---------------------------------------------------------------------------

#define R_MAX      512
#define B_MAX      256
#define NODE_WORDS 4096          // bitmap capacity: 131072 node ids
#define SLOT_CAP   131072

__device__ int      g_node_slot[SLOT_CAP];
__device__ unsigned g_bitmap[NODE_WORDS];
__device__ int      g_counts[B_MAX * R_MAX];
__device__ int      g_relcnt[R_MAX];

// ---------------------------------------------------------------------------
// K1 (fused init+scatter, vectorized)
// ---------------------------------------------------------------------------
__global__ void k_init_scatter(const int* __restrict__ query_entities, int B) {
    if (blockIdx.x == 0) {
        int4 z4 = make_int4(0, 0, 0, 0);
        int4* bm4 = (int4*)g_bitmap;              // 4096 words = 1024 int4
        for (int i = threadIdx.x; i < NODE_WORDS / 4; i += 256) bm4[i] = z4;
        int4* rc4 = (int4*)g_relcnt;              // 512 words = 128 int4
        if (threadIdx.x < R_MAX / 4) rc4[threadIdx.x] = z4;
        __syncthreads();
        int b = threadIdx.x;
        int e = (b < B) ? query_entities[b] : -1;
        if (b < B) g_node_slot[e] = 0x7fffffff;
        __syncthreads();
        if (b < B) {
            atomicOr(&g_bitmap[e >> 5], 1u << (e & 31));
            atomicMin(&g_node_slot[e], b);
        }
    } else {
        int i = (blockIdx.x - 1) * 256 + threadIdx.x;
        ((int4*)g_counts)[i] = make_int4(0, 0, 0, 0);
    }
}

// ---------------------------------------------------------------------------
// K3: streaming edge scan with next-quad prefetch (MLP 3 -> 6)
// ---------------------------------------------------------------------------
__global__ void __launch_bounds__(256) k_scan(const int* __restrict__ heads,
                                              const int* __restrict__ tails,
                                              const int* __restrict__ types,
                                              int E, int R) {
    __shared__ unsigned bm[NODE_WORDS];
    __shared__ int hist[R_MAX];
    for (int i = threadIdx.x; i < NODE_WORDS; i += blockDim.x) bm[i] = g_bitmap[i];
    for (int i = threadIdx.x; i < R_MAX;      i += blockDim.x) hist[i] = 0;
    __syncthreads();

    auto proc = [&](int hh, int tt, int rr) {
        atomicAdd(&hist[rr], 1);
        if ((bm[hh >> 5] >> (hh & 31)) & 1u)
            atomicAdd(&g_counts[__ldg(&g_node_slot[hh]) * R_MAX + rr], 1);
        if (hh != tt && ((bm[tt >> 5] >> (tt & 31)) & 1u))
            atomicAdd(&g_counts[__ldg(&g_node_slot[tt]) * R_MAX + rr], 1);
    };
    auto proc4 = [&](int4 h, int4 t, int4 r) {
        proc(h.x, t.x, r.x);
        proc(h.y, t.y, r.y);
        proc(h.z, t.z, r.z);
        proc(h.w, t.w, r.w);
    };

    bool vec_ok = ((E & 3) == 0);
    if (vec_ok) {
        int quads = E >> 2;
        const int4* h4 = (const int4*)heads;
        const int4* t4 = (const int4*)tails;
        const int4* r4 = (const int4*)types;
        int stride = gridDim.x * blockDim.x;
        int q = blockIdx.x * blockDim.x + threadIdx.x;
        if (q < quads) {
            int4 h = h4[q], t = t4[q], r = r4[q];
            for (int qn = q + stride; qn < quads; qn += stride) {
                int4 hn = h4[qn], tn = t4[qn], rn = r4[qn];  // prefetch next
                proc4(h, t, r);
                h = hn; t = tn; r = rn;
            }
            proc4(h, t, r);
        }
    } else {
        for (int e = blockIdx.x * blockDim.x + threadIdx.x; e < E;
             e += gridDim.x * blockDim.x) {
            proc(heads[e], tails[e], types[e]);
        }
    }

    __syncthreads();
    for (int i = threadIdx.x; i < R; i += blockDim.x) {
        int v = hist[i];
        if (v) atomicAdd(&g_relcnt[i], v);
    }
}

// ---------------------------------------------------------------------------
// K4: TWO queries per block (512 thr, 128 blocks -> single wave).
//  Each 256-thread half runs the full pipeline for one query; barrier phases
//  are aligned so block-wide __syncthreads works for both halves.
// ---------------------------------------------------------------------------
__global__ void __launch_bounds__(512) k_gate(const float* __restrict__ rel_emb,
                                              const int* __restrict__ query_rels,
                                              const int* __restrict__ query_entities,
                                              const float* __restrict__ W1, const float* __restrict__ b1,
                                              const float* __restrict__ W2, const float* __restrict__ b2,
                                              const float* __restrict__ W3, const float* __restrict__ b3,
                                              const float* __restrict__ W4, const float* __restrict__ b4,
                                              float* __restrict__ out,
                                              int R, int D, int E,
                                              const int* __restrict__ num_nodes_ptr,
                                              int n_default, int B) {
    int t = threadIdx.x;                 // 0..511
    int half = t >> 8;                   // 0 or 1
    int u = t & 255;                     // index within half
    int q = blockIdx.x * 2 + half;       // query id
    int lane = u & 31;
    int hw  = u >> 5;                    // warp within half: 0..7
    bool active = (q < B);

    __shared__ float s_val[2][R_MAX];
    __shared__ int   s_idx[2][R_MAX];
    __shared__ int   s_wcnt0[2][8], s_wcnt1[2][8];
    __shared__ int   s_woff0[2][8], s_woff1[2][8];
    __shared__ int   s_nnz[2];
    __shared__ float s_part[2][8][64];
    __shared__ float s_p1[2][4][64];
    __shared__ float s_p2[2][8][32];
    __shared__ float s_p3[2][16][16];
    __shared__ float s_x[2][132];
    __shared__ float s_h1[2][64];
    __shared__ float s_h2[2][32];
    __shared__ float s_g[2][16];
    __shared__ float s_wsum[2][8];
    __shared__ float s_deg[2];

    int qe = active ? query_entities[q] : 0;
    int qr = active ? query_rels[q] : 0;
    const float* emb = rel_emb + (size_t)q * (size_t)R_MAX * 64;

    // early independent loads
    float qv = 0.f;
    if (active && u < 64) qv = __ldg(&emb[qr * 64 + u]);
    float rc = (active && u == 0) ? (float)__ldg(&g_relcnt[qr]) : 0.f;

    float c0 = 0.f, c1 = 0.f;
    if (active) {
        int slot = g_node_slot[qe];
        const int* cnt_row = &g_counts[slot * R_MAX];
        c0 = (float)cnt_row[u];
        c1 = (float)cnt_row[u + 256];
    }

    // degree reduction
    float part = c0 + c1;
    #pragma unroll
    for (int off = 16; off > 0; off >>= 1)
        part += __shfl_xor_sync(0xffffffffu, part, off);
    if (lane == 0) s_wsum[half][hw] = part;

    // single-pass deterministic compaction (both halves of count row)
    bool p0 = (c0 != 0.f);
    bool p1 = (c1 != 0.f);
    unsigned m0 = __ballot_sync(0xffffffffu, p0);
    unsigned m1 = __ballot_sync(0xffffffffu, p1);
    int wp0 = __popc(m0 & ((1u << lane) - 1u));
    int wp1 = __popc(m1 & ((1u << lane) - 1u));
    if (lane == 0) { s_wcnt0[half][hw] = __popc(m0); s_wcnt1[half][hw] = __popc(m1); }
    __syncthreads();
    if (u == 0) {
        int o = 0;
        #pragma unroll
        for (int w = 0; w < 8; w++) { s_woff0[half][w] = o; o += s_wcnt0[half][w]; }
        #pragma unroll
        for (int w = 0; w < 8; w++) { s_woff1[half][w] = o; o += s_wcnt1[half][w]; }
        s_nnz[half] = o;
        float d = 0.f;
        #pragma unroll
        for (int w = 0; w < 8; w++) d += s_wsum[half][w];
        s_deg[half] = d;
    }
    __syncthreads();
    if (p0) { int p = s_woff0[half][hw] + wp0; s_idx[half][p] = u;       s_val[half][p] = c0; }
    if (p1) { int p = s_woff1[half][hw] + wp1; s_idx[half][p] = 256 + u; s_val[half][p] = c1; }
    __syncthreads();

    int nnz = s_nnz[half];
    float deg = s_deg[half];
    float inv = 1.0f / fmaxf(deg, 1.0f);

    // gather: warp hw handles rows hw, hw+8, ...; lane -> 2 dims
    {
        float ax = 0.f, ay = 0.f;
        if (active) {
            #pragma unroll 8
            for (int i = hw; i < nnz; i += 8) {
                float v = s_val[half][i];
                float2 d = __ldg((const float2*)(emb + s_idx[half][i] * 64) + lane);
                ax += v * d.x;
                ay += v * d.y;
            }
        }
        s_part[half][hw][lane * 2]     = ax;
        s_part[half][hw][lane * 2 + 1] = ay;
    }
    __syncthreads();

    if (u < 64) {
        float a = 0.f;
        #pragma unroll
        for (int w = 0; w < 8; w++) a += s_part[half][w][u];
        s_x[half][u]      = qv;
        s_x[half][64 + u] = a * inv;
    }
    if (u == 0) {
        float Ef   = (float)E;
        float freq = fminf(rc / Ef, 1.0f);
        float degn = fminf(deg / Ef, 1.0f);
        int   N    = num_nodes_ptr ? *num_nodes_ptr : n_default;
        float density = fminf(Ef / ((float)N * (float)N), 1.0f);
        s_x[half][128 + 0] = freq;
        s_x[half][128 + 1] = degn;
        s_x[half][128 + 2] = freq;
        s_x[half][128 + 3] = density;
    }
    __syncthreads();

    // W1: 132 -> 64, 4-way i-split (33 each) over the half's 256 threads
    {
        int jj = u & 63, g = u >> 6;
        float p = 0.f;
        #pragma unroll
        for (int k = 0; k < 33; k++) {
            int i = g * 33 + k;
            p += s_x[half][i] * __ldg(&W1[i * 64 + jj]);
        }
        s_p1[half][g][jj] = p;
    }
    __syncthreads();
    if (u < 64)
        s_h1[half][u] = fmaxf(__ldg(&b1[u]) + s_p1[half][0][u] + s_p1[half][1][u]
                              + s_p1[half][2][u] + s_p1[half][3][u], 0.f);
    __syncthreads();

    // W2: 64 -> 32, 8-way i-split
    {
        int o = u & 31, g = u >> 5;
        float p = 0.f;
        #pragma unroll
        for (int k = 0; k < 8; k++) {
            int i = g * 8 + k;
            p += s_h1[half][i] * __ldg(&W2[i * 32 + o]);
        }
        s_p2[half][g][o] = p;
    }
    __syncthreads();
    if (u < 32) {
        float a = __ldg(&b2[u]);
        #pragma unroll
        for (int w = 0; w < 8; w++) a += s_p2[half][w][u];
        s_h2[half][u] = fmaxf(a, 0.f);
    }
    __syncthreads();

    // W3: 32 -> 16, 16-way i-split
    {
        int o = u & 15, g = u >> 4;
        int i0 = 2 * g, i1 = 2 * g + 1;
        s_p3[half][g][o] = s_h2[half][i0] * __ldg(&W3[i0 * 16 + o])
                         + s_h2[half][i1] * __ldg(&W3[i1 * 16 + o]);
    }
    __syncthreads();
    if (u < 16) {
        float a = __ldg(&b3[u]);
        #pragma unroll
        for (int w = 0; w < 16; w++) a += s_p3[half][w][u];
        s_g[half][u] = fmaxf(a, 0.f);
    }
    __syncthreads();

    // W4: 16 -> 1 via warp shuffle in each half's warp 0
    if (u < 32) {
        float v = (u < 16) ? s_g[half][u] * __ldg(&W4[u]) : 0.f;
        #pragma unroll
        for (int off = 8; off > 0; off >>= 1)
            v += __shfl_xor_sync(0xffffffffu, v, off);
        if (u == 0 && active) out[q] = 1.0f / (1.0f + expf(-(v + __ldg(&b4[0]))));
    }
}

// ---------------------------------------------------------------------------
// Host launcher (graph-capturable: kernel launches only, default stream)
// ---------------------------------------------------------------------------
extern "C" void kernel_launch(void* const* d_in, const int* in_sizes, int n_in,
                              void* d_out, int out_size) {
    const float* rel_emb    = (const float*)d_in[0];
    const int*   qrels      = (const int*)d_in[1];
    const int*   qents      = (const int*)d_in[2];
    const int*   edge_index = (const int*)d_in[3];
    const int*   edge_type  = (const int*)d_in[4];

    int B = in_sizes[1];
    int E = in_sizes[4];

    int i = 5;
    const int* num_nodes_ptr = nullptr;
    while (i < n_in && in_sizes[i] == 1) {
        if (num_nodes_ptr == nullptr) num_nodes_ptr = (const int*)d_in[i];
        i++;
    }
    const float* W1 = (const float*)d_in[i + 0];
    const float* b1 = (const float*)d_in[i + 1];
    const float* W2 = (const float*)d_in[i + 2];
    const float* b2 = (const float*)d_in[i + 3];
    const float* W3 = (const float*)d_in[i + 4];
    const float* b3 = (const float*)d_in[i + 5];
    const float* W4 = (const float*)d_in[i + 6];
    const float* b4 = (const float*)d_in[i + 7];

    int D = in_sizes[i + 1];             // 64
    int R = in_sizes[0] / (B * D);       // 512

    k_init_scatter<<<129, 256>>>(qents, B);
    k_scan<<<1184, 256>>>(edge_index, edge_index + E, edge_type, E, R);
    k_gate<<<(B + 1) / 2, 512>>>(rel_emb, qrels, qents,
                                 W1, b1, W2, b2, W3, b3, W4, b4,
                                 (float*)d_out, R, D, E, num_nodes_ptr, 100000, B);
}